// round 1
// baseline (speedup 1.0000x reference)
#include <cuda_runtime.h>
#include <cuda_bf16.h>
#include <cstdint>

// Problem constants (shapes are fixed by the reference)
#define DIM        4096
#define N_HEADS    32
#define HEAD_DIM   128
#define N_KV       8
#define B          8
#define UP_OUT     (N_KV * HEAD_DIM)   // 1024

// Scratch (allocation-free rule: __device__ globals)
__device__ float g_x[B * UP_OUT];      // up-projection result  [8, 1024]
__device__ float g_y[B * DIM];         // down-projection result [8, 4096]
__device__ int   g_rowstart[B + 1];    // token prefix offsets

// ---------------------------------------------------------------------------
// Setup: build row-start prefix from seqlen. Handles int32 OR int64 layout by
// checking which interpretation sums to the true token count (out_size/DIM).
// ---------------------------------------------------------------------------
__global__ void setup_prefix(const void* __restrict__ seqlen_raw, int total_tokens) {
    const int*       s32 = (const int*)seqlen_raw;
    const long long* s64 = (const long long*)seqlen_raw;
    long long sum64 = 0;
    for (int i = 0; i < B; i++) sum64 += s64[i];
    bool use64 = (sum64 == (long long)total_tokens);
    int acc = 0;
    for (int i = 0; i < B; i++) {
        g_rowstart[i] = acc;
        acc += use64 ? (int)s64[i] : s32[i];
    }
    g_rowstart[B] = acc;
}

// ---------------------------------------------------------------------------
// Up GEMV: x[b, j] = dot(emb[b, :], W_up[j, :])  for all 8 b per warp.
// One warp per output column j (1024 warps). Coalesced float4 row reads.
// ---------------------------------------------------------------------------
__global__ void up_gemv(const float* __restrict__ emb,
                        const float* __restrict__ Wup) {
    int warp = (blockIdx.x * blockDim.x + threadIdx.x) >> 5;
    int lane = threadIdx.x & 31;
    if (warp >= UP_OUT) return;

    const float4* wrow = (const float4*)(Wup + (size_t)warp * DIM);
    float acc[B];
#pragma unroll
    for (int b = 0; b < B; b++) acc[b] = 0.f;

    for (int c = lane; c < DIM / 4; c += 32) {
        float4 w = __ldg(&wrow[c]);
#pragma unroll
        for (int b = 0; b < B; b++) {
            float4 e = __ldg((const float4*)(emb + (size_t)b * DIM) + c);
            acc[b] += e.x * w.x + e.y * w.y + e.z * w.z + e.w * w.w;
        }
    }
#pragma unroll
    for (int b = 0; b < B; b++) {
#pragma unroll
        for (int off = 16; off > 0; off >>= 1)
            acc[b] += __shfl_down_sync(0xffffffffu, acc[b], off);
    }
    if (lane == 0) {
#pragma unroll
        for (int b = 0; b < B; b++) g_x[b * UP_OUT + warp] = acc[b];
    }
}

// ---------------------------------------------------------------------------
// Down GEMV: y[b, o] = sum_i val[b, i] * W_down[o, i]
// val[b, i] = x[b, ((i>>9)<<7) | (i&127)]  (repeat-interleave folded in).
// One warp per output column o (4096 warps), all 8 b accumulated per warp.
// W_down row (16 KB) read exactly once; x (32 KB) L1-resident.
// ---------------------------------------------------------------------------
__global__ void down_gemv(const float* __restrict__ Wdown) {
    int warp = (blockIdx.x * blockDim.x + threadIdx.x) >> 5;
    int lane = threadIdx.x & 31;
    if (warp >= DIM) return;

    const float4* wrow = (const float4*)(Wdown + (size_t)warp * DIM);
    float acc[B];
#pragma unroll
    for (int b = 0; b < B; b++) acc[b] = 0.f;

    for (int c = lane; c < DIM / 4; c += 32) {
        float4 w = __ldg(&wrow[c]);
        int i  = c * 4;                          // i .. i+3 stay within one head (128 | 4)
        int xi = ((i >> 9) << 7) | (i & 127);    // map head -> kv head
#pragma unroll
        for (int b = 0; b < B; b++) {
            float4 v = *(const float4*)(g_x + b * UP_OUT + xi);
            acc[b] += v.x * w.x + v.y * w.y + v.z * w.z + v.w * w.w;
        }
    }
#pragma unroll
    for (int b = 0; b < B; b++) {
#pragma unroll
        for (int off = 16; off > 0; off >>= 1)
            acc[b] += __shfl_down_sync(0xffffffffu, acc[b], off);
    }
    if (lane == 0) {
#pragma unroll
        for (int b = 0; b < B; b++) g_y[b * DIM + warp] = acc[b];
    }
}

// ---------------------------------------------------------------------------
// Broadcast: out[t, :] = y[batch(t), :].  One block per token; y is 128 KB
// (L2-resident after first wave). Pure store-bandwidth bound: 268 MB.
// ---------------------------------------------------------------------------
__global__ void broadcast_rows(float4* __restrict__ out) {
    int t = blockIdx.x;
    int b = 0;
#pragma unroll
    for (int k = 1; k < B; k++) b += (t >= g_rowstart[k]);

    const float4* yrow = (const float4*)(g_y + (size_t)b * DIM);
    float4*       orow = out + (size_t)t * (DIM / 4);
#pragma unroll
    for (int c = threadIdx.x; c < DIM / 4; c += 256)
        orow[c] = __ldg(&yrow[c]);
}

// ---------------------------------------------------------------------------
extern "C" void kernel_launch(void* const* d_in, const int* in_sizes, int n_in,
                              void* d_out, int out_size) {
    const float* emb   = (const float*)d_in[0];  // [8, 4096]
    const float* Wup   = (const float*)d_in[1];  // [1024, 4096]
    const float* Wdown = (const float*)d_in[2];  // [4096, 4096]
    const void*  seql  = d_in[3];                // [8] int32 or int64

    int total_tokens = out_size / DIM;           // 16384

    setup_prefix<<<1, 1>>>(seql, total_tokens);
    up_gemv<<<(UP_OUT * 32 + 255) / 256, 256>>>(emb, Wup);     // 1024 warps
    down_gemv<<<(DIM * 32 + 255) / 256, 256>>>(Wdown);         // 4096 warps
    broadcast_rows<<<total_tokens, 256>>>((float4*)d_out);
}

// round 2
// speedup vs baseline: 1.2594x; 1.2594x over previous
#include <cuda_runtime.h>
#include <cuda_bf16.h>
#include <cstdint>

#define DIM        4096
#define N_HEADS    32
#define HEAD_DIM   128
#define N_KV       8
#define B          8
#define UP_OUT     (N_KV * HEAD_DIM)   // 1024

// Scratch (allocation-free rule: __device__ globals)
__device__ float g_x[B * UP_OUT];      // up-projection result   [8, 1024]
__device__ float g_y[B * DIM];         // down-projection result [8, 4096]

// ---------------------------------------------------------------------------
// Up GEMV: x[b, j] = dot(emb[b,:], W_up[j,:]) for all 8 b per warp.
// emb (128 KB) staged in dynamic smem; warp per output column j.
// ---------------------------------------------------------------------------
__global__ void up_gemv(const float* __restrict__ emb,
                        const float* __restrict__ Wup) {
    extern __shared__ float semb[];                 // 8*4096 floats = 128 KB
    {
        const float4* src = (const float4*)emb;
        float4*       dst = (float4*)semb;
        for (int i = threadIdx.x; i < B * DIM / 4; i += blockDim.x)
            dst[i] = src[i];
    }
    __syncthreads();

    int warp = (blockIdx.x * blockDim.x + threadIdx.x) >> 5;
    int lane = threadIdx.x & 31;
    if (warp >= UP_OUT) return;

    const float4* wrow = (const float4*)(Wup + (size_t)warp * DIM);
    float acc[B];
#pragma unroll
    for (int b = 0; b < B; b++) acc[b] = 0.f;

#pragma unroll 4
    for (int c = lane; c < DIM / 4; c += 32) {
        float4 w = __ldg(&wrow[c]);
#pragma unroll
        for (int b = 0; b < B; b++) {
            float4 e = ((const float4*)semb)[b * (DIM / 4) + c];
            acc[b] += e.x * w.x + e.y * w.y + e.z * w.z + e.w * w.w;
        }
    }
#pragma unroll
    for (int b = 0; b < B; b++) {
#pragma unroll
        for (int off = 16; off > 0; off >>= 1)
            acc[b] += __shfl_down_sync(0xffffffffu, acc[b], off);
    }
    if (lane == 0) {
#pragma unroll
        for (int b = 0; b < B; b++) g_x[b * UP_OUT + warp] = acc[b];
    }
}

// ---------------------------------------------------------------------------
// Down GEMV: y[b, o] = sum_i val[b,i] * W_down[o,i],
// val[b,i] = x[b, ((i>>9)<<7) | (i&127)]  (repeat-interleave folded in).
// g_x (32 KB) staged in static smem per block; warp per output column o.
// W_down row (16 KB) streamed once, unroll 4 for MLP.
// ---------------------------------------------------------------------------
__global__ __launch_bounds__(256) void down_gemv(const float* __restrict__ Wdown) {
    __shared__ float sx[B * UP_OUT];                // 32 KB
    {
        const float4* src = (const float4*)g_x;
        float4*       dst = (float4*)sx;
        for (int i = threadIdx.x; i < B * UP_OUT / 4; i += 256)
            dst[i] = src[i];
    }
    __syncthreads();

    int warp = (blockIdx.x * 256 + threadIdx.x) >> 5;
    int lane = threadIdx.x & 31;
    if (warp >= DIM) return;

    const float4* wrow = (const float4*)(Wdown + (size_t)warp * DIM);
    float acc[B];
#pragma unroll
    for (int b = 0; b < B; b++) acc[b] = 0.f;

#pragma unroll 4
    for (int c = lane; c < DIM / 4; c += 32) {
        float4 w = __ldg(&wrow[c]);
        int i  = c * 4;                           // i..i+3 within one head (128 | 4)
        int xi = ((i >> 9) << 7) | (i & 127);     // head -> kv head
#pragma unroll
        for (int b = 0; b < B; b++) {
            float4 v = *(const float4*)(sx + b * UP_OUT + xi);
            acc[b] += v.x * w.x + v.y * w.y + v.z * w.z + v.w * w.w;
        }
    }
#pragma unroll
    for (int b = 0; b < B; b++) {
#pragma unroll
        for (int off = 16; off > 0; off >>= 1)
            acc[b] += __shfl_down_sync(0xffffffffu, acc[b], off);
    }
    if (lane == 0) {
#pragma unroll
        for (int b = 0; b < B; b++) g_y[b * DIM + warp] = acc[b];
    }
}

// ---------------------------------------------------------------------------
// Broadcast: out[t, :] = y[batch(t), :]. One block per token.
// Prefix scan over seqlen folded in (thread 0, smem broadcast); handles
// int32 OR int64 seqlen by checking which sums to the true token count.
// Streaming stores (__stcs): out is write-once, never re-read.
// ---------------------------------------------------------------------------
__global__ __launch_bounds__(256) void broadcast_rows(float4* __restrict__ out,
                                                      const void* __restrict__ seqlen_raw,
                                                      int total_tokens) {
    __shared__ int sb;
    if (threadIdx.x == 0) {
        const int*       s32 = (const int*)seqlen_raw;
        const long long* s64 = (const long long*)seqlen_raw;
        long long sum64 = 0;
#pragma unroll
        for (int i = 0; i < B; i++) sum64 += s64[i];
        bool use64 = (sum64 == (long long)total_tokens);
        int t = blockIdx.x;
        int acc = 0, b = 0;
#pragma unroll
        for (int i = 0; i < B; i++) {
            int len = use64 ? (int)s64[i] : s32[i];
            if (t >= acc + len) b = i + 1;
            acc += len;
        }
        sb = b;
    }
    __syncthreads();

    const float4* yrow = (const float4*)(g_y + (size_t)sb * DIM);
    float4*       orow = out + (size_t)blockIdx.x * (DIM / 4);
#pragma unroll
    for (int c = threadIdx.x; c < DIM / 4; c += 256)
        __stcs(&orow[c], __ldg(&yrow[c]));
}

// ---------------------------------------------------------------------------
extern "C" void kernel_launch(void* const* d_in, const int* in_sizes, int n_in,
                              void* d_out, int out_size) {
    const float* emb   = (const float*)d_in[0];  // [8, 4096]
    const float* Wup   = (const float*)d_in[1];  // [1024, 4096]
    const float* Wdown = (const float*)d_in[2];  // [4096, 4096]
    const void*  seql  = d_in[3];                // [8] int32 or int64

    int total_tokens = out_size / DIM;           // 16384

    static bool attr_set = false;
    if (!attr_set) {
        cudaFuncSetAttribute(up_gemv, cudaFuncAttributeMaxDynamicSharedMemorySize,
                             B * DIM * (int)sizeof(float));
        attr_set = true;
    }

    up_gemv<<<(UP_OUT * 32 + 255) / 256, 256, B * DIM * sizeof(float)>>>(emb, Wup);
    down_gemv<<<(DIM * 32 + 255) / 256, 256>>>(Wdown);
    broadcast_rows<<<total_tokens, 256>>>((float4*)d_out, seql, total_tokens);
}

// round 3
// speedup vs baseline: 1.5864x; 1.2596x over previous
#include <cuda_runtime.h>
#include <cuda_bf16.h>
#include <cstdint>

#define DIM        4096
#define N_HEADS    32
#define HEAD_DIM   128
#define N_KV       8
#define B          8
#define UP_OUT     (N_KV * HEAD_DIM)   // 1024
#define KSPLIT     4                   // K-chunks for up-projection

// Scratch (allocation-free rule: __device__ globals)
__device__ float g_xp[KSPLIT][B * UP_OUT]; // up-projection partials [4][8,1024]
__device__ float g_y[B * DIM];             // down-projection result [8, 4096]

// ---------------------------------------------------------------------------
// Up GEMV (K-split partials): xp[s][b,j] = dot(emb[b, s*1024:(s+1)*1024],
//                                              W_up[j, s*1024:(s+1)*1024]).
// 4096 warps (512 blocks): warp -> (column j, chunk s). emb is 128 KB and
// L2-resident, loaded directly via __ldg. Each warp streams 4 KB of W_up.
// ---------------------------------------------------------------------------
__global__ __launch_bounds__(256) void up_gemv(const float* __restrict__ emb,
                                               const float* __restrict__ Wup) {
    int gw   = (blockIdx.x * 256 + threadIdx.x) >> 5;  // 0..4095
    int lane = threadIdx.x & 31;
    int j = gw >> 2;          // output column 0..1023
    int s = gw & 3;           // K chunk 0..3

    const int CHUNK4 = DIM / 4 / KSPLIT;               // 256 float4
    const float4* wrow = (const float4*)(Wup + (size_t)j * DIM) + s * CHUNK4;
    const float4* e4   = (const float4*)emb;

    float acc[B];
#pragma unroll
    for (int b = 0; b < B; b++) acc[b] = 0.f;

#pragma unroll 4
    for (int c = lane; c < CHUNK4; c += 32) {
        float4 w = __ldg(&wrow[c]);
        int ec = s * CHUNK4 + c;
#pragma unroll
        for (int b = 0; b < B; b++) {
            float4 e = __ldg(&e4[b * (DIM / 4) + ec]);
            acc[b] += e.x * w.x + e.y * w.y + e.z * w.z + e.w * w.w;
        }
    }
#pragma unroll
    for (int b = 0; b < B; b++) {
#pragma unroll
        for (int off = 16; off > 0; off >>= 1)
            acc[b] += __shfl_down_sync(0xffffffffu, acc[b], off);
    }
    if (lane == 0) {
#pragma unroll
        for (int b = 0; b < B; b++) g_xp[s][b * UP_OUT + j] = acc[b];
    }
}

// ---------------------------------------------------------------------------
// Down GEMV: y[b, o] = sum_i val[b,i] * W_down[o,i],
// val[b,i] = x[b, ((i>>9)<<7) | (i&127)]  (repeat-interleave folded in).
// Staging sums the 4 up-partials into smem (L2 reads, overlapped with the
// W_down DRAM stream). Warp per output column, unroll-8 on the W stream.
// ---------------------------------------------------------------------------
__global__ __launch_bounds__(256) void down_gemv(const float* __restrict__ Wdown) {
    __shared__ float sx[B * UP_OUT];                   // 32 KB
    {
        float4* dst = (float4*)sx;
        for (int i = threadIdx.x; i < B * UP_OUT / 4; i += 256) {
            float4 a = __ldg((const float4*)g_xp[0] + i);
            float4 b = __ldg((const float4*)g_xp[1] + i);
            float4 c = __ldg((const float4*)g_xp[2] + i);
            float4 d = __ldg((const float4*)g_xp[3] + i);
            float4 r;
            r.x = (a.x + b.x) + (c.x + d.x);
            r.y = (a.y + b.y) + (c.y + d.y);
            r.z = (a.z + b.z) + (c.z + d.z);
            r.w = (a.w + b.w) + (c.w + d.w);
            dst[i] = r;
        }
    }
    __syncthreads();

    int warp = (blockIdx.x * 256 + threadIdx.x) >> 5;  // 0..4095
    int lane = threadIdx.x & 31;

    const float4* wrow = (const float4*)(Wdown + (size_t)warp * DIM);
    float acc[B];
#pragma unroll
    for (int b = 0; b < B; b++) acc[b] = 0.f;

#pragma unroll 8
    for (int c = lane; c < DIM / 4; c += 32) {
        float4 w = __ldg(&wrow[c]);
        int i  = c * 4;                            // i..i+3 within one head (128 | 4)
        int xi = ((i >> 9) << 7) | (i & 127);      // head -> kv head
#pragma unroll
        for (int b = 0; b < B; b++) {
            float4 v = *(const float4*)(sx + b * UP_OUT + xi);
            acc[b] += v.x * w.x + v.y * w.y + v.z * w.z + v.w * w.w;
        }
    }
#pragma unroll
    for (int b = 0; b < B; b++) {
#pragma unroll
        for (int off = 16; off > 0; off >>= 1)
            acc[b] += __shfl_down_sync(0xffffffffu, acc[b], off);
    }
    if (lane == 0) {
#pragma unroll
        for (int b = 0; b < B; b++) g_y[b * DIM + warp] = acc[b];
    }
}

// ---------------------------------------------------------------------------
// Broadcast: out[t, :] = y[batch(t), :]. One block per token; streaming
// stores (out is write-once). Prefix scan over seqlen folded in; handles
// int32 OR int64 seqlen by checking which sums to the true token count.
// ---------------------------------------------------------------------------
__global__ __launch_bounds__(256) void broadcast_rows(float4* __restrict__ out,
                                                      const void* __restrict__ seqlen_raw,
                                                      int total_tokens) {
    __shared__ int sb;
    if (threadIdx.x == 0) {
        const int*       s32 = (const int*)seqlen_raw;
        const long long* s64 = (const long long*)seqlen_raw;
        long long sum64 = 0;
#pragma unroll
        for (int i = 0; i < B; i++) sum64 += s64[i];
        bool use64 = (sum64 == (long long)total_tokens);
        int t = blockIdx.x;
        int acc = 0, b = 0;
#pragma unroll
        for (int i = 0; i < B; i++) {
            int len = use64 ? (int)s64[i] : s32[i];
            if (t >= acc + len) b = i + 1;
            acc += len;
        }
        sb = b;
    }
    __syncthreads();

    const float4* yrow = (const float4*)(g_y + (size_t)sb * DIM);
    float4*       orow = out + (size_t)blockIdx.x * (DIM / 4);
#pragma unroll
    for (int c = threadIdx.x; c < DIM / 4; c += 256)
        __stcs(&orow[c], __ldg(&yrow[c]));
}

// ---------------------------------------------------------------------------
extern "C" void kernel_launch(void* const* d_in, const int* in_sizes, int n_in,
                              void* d_out, int out_size) {
    const float* emb   = (const float*)d_in[0];  // [8, 4096]
    const float* Wup   = (const float*)d_in[1];  // [1024, 4096]
    const float* Wdown = (const float*)d_in[2];  // [4096, 4096]
    const void*  seql  = d_in[3];                // [8] int32 or int64

    int total_tokens = out_size / DIM;           // 16384

    up_gemv<<<UP_OUT * KSPLIT / 8, 256>>>(emb, Wup);   // 512 blocks, 4096 warps
    down_gemv<<<DIM / 8, 256>>>(Wdown);                // 512 blocks, 4096 warps
    broadcast_rows<<<total_tokens, 256>>>((float4*)d_out, seql, total_tokens);
}